// round 2
// baseline (speedup 1.0000x reference)
#include <cuda_runtime.h>
#include <math.h>

// ---------------- problem constants ----------------
#define NDRUG   11000
#define NPRO    1000
#define NTOT    12000
#define EMB     128
#define H1DIM   256
#define H2DIM   128
#define NEDGE   192000
#define OFF_MU  144000000         // 12000*12000
#define OFF_LV  145536000         // + 12000*128

// ---------------- scratch (__device__ globals; no allocation allowed) -------
__device__ float g_d1[NDRUG * EMB];        // drug layer1 out
__device__ float g_d2[NDRUG * 2 * EMB];    // drug layer2 out
__device__ float g_x [NTOT  * EMB];        // concat(d, p)
__device__ float g_xw[NTOT  * H1DIM];      // x @ gc1_w
__device__ float g_h1[NTOT  * H1DIM];      // spmm accum -> relu
__device__ float g_t1[NTOT  * H2DIM];      // h1 @ gc2_w
__device__ float g_t2[NTOT  * H2DIM];      // h1 @ gc3_w
__device__ float g_T [NPRO  * 6656];       // [p][(o*8+k)*26+v]
__device__ float g_U [6656  * EMB];        // [(o*8+k)*26+v][e]
__device__ float g_cb[EMB];                // folded conv_b/fc_b bias

// ---------------- utility kernels ----------------
__global__ void zero2_kernel(float* a, float* b, int n) {
    int i = blockIdx.x * blockDim.x + threadIdx.x;
    if (i < n) { a[i] = 0.f; b[i] = 0.f; }
}

__global__ void relu_kernel(float* x, int n) {
    int i = blockIdx.x * blockDim.x + threadIdx.x;
    if (i < n) x[i] = fmaxf(x[i], 0.f);
}

// ---------------- generic fp32 GEMM: C[M,N] = A[M,K] @ B[K,N] (+bias, relu) -
// 64x64 tile, BK=16, 256 threads, 4x4 micro-tile
__global__ __launch_bounds__(256) void gemm_kernel(
    const float* __restrict__ A, const float* __restrict__ B,
    const float* __restrict__ bias, float* __restrict__ C,
    int M, int N, int K, int do_relu)
{
    __shared__ float As[16][68];
    __shared__ float Bs[16][68];
    int tid = threadIdx.x;
    int tx = tid & 15, ty = tid >> 4;
    int bm = blockIdx.y * 64, bn = blockIdx.x * 64;
    float acc[4][4] = {};

    for (int k0 = 0; k0 < K; k0 += 16) {
#pragma unroll
        for (int l = 0; l < 4; l++) {           // A tile 64x16
            int e = tid + l * 256;
            int m = e >> 4, k = e & 15;
            int r = bm + m, kk = k0 + k;
            As[k][m] = (r < M && kk < K) ? A[(size_t)r * K + kk] : 0.f;
        }
#pragma unroll
        for (int l = 0; l < 4; l++) {           // B tile 16x64
            int e = tid + l * 256;
            int k = e >> 6, n = e & 63;
            int kk = k0 + k, c = bn + n;
            Bs[k][n] = (kk < K && c < N) ? B[(size_t)kk * N + c] : 0.f;
        }
        __syncthreads();
#pragma unroll
        for (int k = 0; k < 16; k++) {
            float a[4], b[4];
#pragma unroll
            for (int i = 0; i < 4; i++) a[i] = As[k][ty * 4 + i];
#pragma unroll
            for (int j = 0; j < 4; j++) b[j] = Bs[k][tx * 4 + j];
#pragma unroll
            for (int i = 0; i < 4; i++)
#pragma unroll
                for (int j = 0; j < 4; j++) acc[i][j] += a[i] * b[j];
        }
        __syncthreads();
    }
#pragma unroll
    for (int i = 0; i < 4; i++) {
        int r = bm + ty * 4 + i;
        if (r >= M) continue;
#pragma unroll
        for (int j = 0; j < 4; j++) {
            int c = bn + tx * 4 + j;
            if (c >= N) continue;
            float v = acc[i][j];
            if (bias) v += bias[c];
            if (do_relu) v = fmaxf(v, 0.f);
            C[(size_t)r * N + c] = v;
        }
    }
}

// ---------------- protein branch ----------------
// T[p,(o*8+k)*26+v] = sum_{i: pro_x[p,i]==v} conv_w[o,i,k]
__global__ __launch_bounds__(256) void tbuild_kernel(
    const int* __restrict__ pro_x, const float* __restrict__ conv_w,
    float* __restrict__ T)
{
    __shared__ float acc[6656];            // 256 threads x 26 private slots
    int p = blockIdx.x, tid = threadIdx.x;
    float* a = acc + tid * 26;
#pragma unroll
    for (int v = 0; v < 26; v++) a[v] = 0.f;
    const float* cw = conv_w + (tid >> 3) * 8000 + (tid & 7);   // [o][i][k]
    const int* px = pro_x + p * 1000;
#pragma unroll 4
    for (int i = 0; i < 1000; i++) {
        int v = px[i];                     // broadcast load
        a[v] += cw[i * 8];
    }
    float* out = T + (size_t)p * 6656 + tid * 26;
#pragma unroll
    for (int v = 0; v < 26; v++) out[v] = a[v];
}

// U[(o*8+k)*26+v][e] = sum_t emb_xt[v][t+k] * fc_w[o*121+t][e]
__global__ __launch_bounds__(128) void ubuild_kernel(
    const float* __restrict__ emb_xt, const float* __restrict__ fc_w,
    float* __restrict__ U)
{
    __shared__ float emb_s[26 * 128];
    int ok = blockIdx.x;            // o*8+k
    int o = ok >> 3, k = ok & 7;
    int e = threadIdx.x;
#pragma unroll
    for (int v = 0; v < 26; v++) emb_s[v * 128 + e] = emb_xt[v * 128 + e];
    __syncthreads();
    float acc[26];
#pragma unroll
    for (int v = 0; v < 26; v++) acc[v] = 0.f;
    for (int t = 0; t < 121; t++) {
        float f = fc_w[(size_t)(o * 121 + t) * 128 + e];
#pragma unroll
        for (int v = 0; v < 26; v++) acc[v] += f * emb_s[v * 128 + t + k];
    }
#pragma unroll
    for (int v = 0; v < 26; v++)
        U[(size_t)(ok * 26 + v) * 128 + e] = acc[v];
}

// cb[e] = fc_b[e] + sum_{o,t} conv_b[o] * fc_w[o*121+t][e]
__global__ void cbias_kernel(const float* __restrict__ fc_w,
                             const float* __restrict__ fc_b,
                             const float* __restrict__ conv_b,
                             float* __restrict__ cb)
{
    int e = threadIdx.x;
    float s = fc_b[e];
    for (int o = 0; o < 32; o++) {
        float cv = conv_b[o];
#pragma unroll 4
        for (int t = 0; t < 121; t++)
            s += cv * fc_w[(size_t)(o * 121 + t) * 128 + e];
    }
    cb[e] = s;
}

// ---------------- SpMM (COO scatter, atomic) ----------------
__global__ void spmm256_kernel(const int* __restrict__ rows, const int* __restrict__ cols,
                               const float* __restrict__ vals,
                               const float* __restrict__ X, float* __restrict__ Y)
{
    int e = blockIdx.x;
    int r = rows[e], c = cols[e];
    float v = vals[e];
    int f = threadIdx.x;
    atomicAdd(&Y[(size_t)r * 256 + f], v * X[(size_t)c * 256 + f]);
}

__global__ void spmm128x2_kernel(const int* __restrict__ rows, const int* __restrict__ cols,
                                 const float* __restrict__ vals,
                                 const float* __restrict__ X1, const float* __restrict__ X2,
                                 float* __restrict__ Y1, float* __restrict__ Y2)
{
    int e = blockIdx.x;
    int r = rows[e], c = cols[e];
    float v = vals[e];
    int f = threadIdx.x;
    atomicAdd(&Y1[(size_t)r * 128 + f], v * X1[(size_t)c * 128 + f]);
    atomicAdd(&Y2[(size_t)r * 128 + f], v * X2[(size_t)c * 128 + f]);
}

// ---------------- adj_rec = Z @ Z^T (symmetric, upper triangle + mirror) ----
// 128x128 tile, BK=16, 256 threads, 8x8 micro-tile
__global__ __launch_bounds__(256) void adjsym_kernel(
    const float* __restrict__ Z, float* __restrict__ C)
{
    const int nt = 94;   // ceil(12000/128)
    int L = blockIdx.x;
    int bi = (int)(nt + 0.5 - sqrt((nt + 0.5) * (nt + 0.5) - 2.0 * (double)L));
    if (bi < 0) bi = 0;
    while ((bi + 1) * nt - ((bi + 1) * bi) / 2 <= L) bi++;
    while (bi * nt - (bi * (bi - 1)) / 2 > L) bi--;
    int bj = bi + (L - (bi * nt - (bi * (bi - 1)) / 2));

    __shared__ float As[16][136];
    __shared__ float Bs[16][136];
    int tid = threadIdx.x;
    int tx = tid & 15, ty = tid >> 4;
    float acc[8][8] = {};
    int rowA0 = bi * 128, rowB0 = bj * 128;

    for (int kc = 0; kc < 128; kc += 16) {
#pragma unroll
        for (int l = 0; l < 8; l++) {
            int e = tid + l * 256;
            int m = e >> 4, k = e & 15;
            int ra = rowA0 + m;
            As[k][m] = (ra < NTOT) ? Z[(size_t)ra * 128 + kc + k] : 0.f;
            int rb = rowB0 + m;
            Bs[k][m] = (rb < NTOT) ? Z[(size_t)rb * 128 + kc + k] : 0.f;
        }
        __syncthreads();
#pragma unroll
        for (int k = 0; k < 16; k++) {
            float a[8], b[8];
#pragma unroll
            for (int i = 0; i < 8; i++) a[i] = As[k][ty * 8 + i];
#pragma unroll
            for (int j = 0; j < 8; j++) b[j] = Bs[k][tx * 8 + j];
#pragma unroll
            for (int i = 0; i < 8; i++)
#pragma unroll
                for (int j = 0; j < 8; j++) acc[i][j] += a[i] * b[j];
        }
        __syncthreads();
    }

    int r0 = rowA0 + ty * 8;
    int c0 = rowB0 + tx * 8;
    bool interior = (rowA0 + 128 <= NTOT) && (rowB0 + 128 <= NTOT);
    if (interior) {
#pragma unroll
        for (int i = 0; i < 8; i++) {
            float4 v0 = make_float4(acc[i][0], acc[i][1], acc[i][2], acc[i][3]);
            float4 v1 = make_float4(acc[i][4], acc[i][5], acc[i][6], acc[i][7]);
            *(float4*)&C[(size_t)(r0 + i) * NTOT + c0]     = v0;
            *(float4*)&C[(size_t)(r0 + i) * NTOT + c0 + 4] = v1;
        }
        if (bi != bj) {
#pragma unroll
            for (int j = 0; j < 8; j++) {
                float4 v0 = make_float4(acc[0][j], acc[1][j], acc[2][j], acc[3][j]);
                float4 v1 = make_float4(acc[4][j], acc[5][j], acc[6][j], acc[7][j]);
                int rr = c0 + j;
                *(float4*)&C[(size_t)rr * NTOT + r0]     = v0;
                *(float4*)&C[(size_t)rr * NTOT + r0 + 4] = v1;
            }
        }
    } else {
        for (int i = 0; i < 8; i++) {
            int r = r0 + i; if (r >= NTOT) break;
            for (int j = 0; j < 8; j++) {
                int c = c0 + j;
                if (c < NTOT) C[(size_t)r * NTOT + c] = acc[i][j];
            }
        }
        if (bi != bj) {
            for (int j = 0; j < 8; j++) {
                int rr = c0 + j; if (rr >= NTOT) break;
                for (int i = 0; i < 8; i++) {
                    int cc = r0 + i;
                    if (cc < NTOT) C[(size_t)rr * NTOT + cc] = acc[i][j];
                }
            }
        }
    }
}

// ---------------- launch ----------------
extern "C" void kernel_launch(void* const* d_in, const int* in_sizes, int n_in,
                              void* d_out, int out_size)
{
    const float* drug_x  = (const float*)d_in[0];
    const int*   pro_x   = (const int*)  d_in[1];
    const int*   adj_r   = (const int*)  d_in[2];
    const int*   adj_c   = (const int*)  d_in[3];
    const float* adj_v   = (const float*)d_in[4];
    const float* w1      = (const float*)d_in[5];
    const float* b1      = (const float*)d_in[6];
    const float* w2      = (const float*)d_in[7];
    const float* b2      = (const float*)d_in[8];
    const float* w3      = (const float*)d_in[9];
    const float* b3      = (const float*)d_in[10];
    const float* emb_xt  = (const float*)d_in[11];
    const float* conv_w  = (const float*)d_in[12];
    const float* conv_b  = (const float*)d_in[13];
    const float* fc_w    = (const float*)d_in[14];
    const float* fc_b    = (const float*)d_in[15];
    const float* gc1_w   = (const float*)d_in[16];
    const float* gc2_w   = (const float*)d_in[17];
    const float* gc3_w   = (const float*)d_in[18];

    float* out = (float*)d_out;
    float* out_mu = out + OFF_MU;
    float* out_lv = out + OFF_LV;

    float *p_d1, *p_d2, *p_x, *p_xw, *p_h1, *p_t1, *p_t2, *p_T, *p_U, *p_cb;
    cudaGetSymbolAddress((void**)&p_d1, g_d1);
    cudaGetSymbolAddress((void**)&p_d2, g_d2);
    cudaGetSymbolAddress((void**)&p_x,  g_x);
    cudaGetSymbolAddress((void**)&p_xw, g_xw);
    cudaGetSymbolAddress((void**)&p_h1, g_h1);
    cudaGetSymbolAddress((void**)&p_t1, g_t1);
    cudaGetSymbolAddress((void**)&p_t2, g_t2);
    cudaGetSymbolAddress((void**)&p_T,  g_T);
    cudaGetSymbolAddress((void**)&p_U,  g_U);
    cudaGetSymbolAddress((void**)&p_cb, g_cb);

    // zero atomic accumulators: h1 (3.072M) and mu+logvar (contiguous 3.072M)
    {
        int n = NTOT * H1DIM;  // 3,072,000 == 2 * 12000 * 128
        zero2_kernel<<<(n + 255) / 256, 256>>>(p_h1, out_mu, n);
    }

    // drug MLP
    gemm_kernel<<<dim3(2, 172), 256>>>(drug_x, w1, b1, p_d1, NDRUG, EMB,   167, 1);
    gemm_kernel<<<dim3(4, 172), 256>>>(p_d1,   w2, b2, p_d2, NDRUG, 2*EMB, EMB, 1);
    gemm_kernel<<<dim3(2, 172), 256>>>(p_d2,   w3, b3, p_x,  NDRUG, EMB, 2*EMB, 1);

    // protein branch (factorized conv+fc)
    tbuild_kernel<<<NPRO, 256>>>(pro_x, conv_w, p_T);
    ubuild_kernel<<<256, 128>>>(emb_xt, fc_w, p_U);
    cbias_kernel<<<1, 128>>>(fc_w, fc_b, conv_b, p_cb);
    gemm_kernel<<<dim3(2, 16), 256>>>(p_T, p_U, p_cb, p_x + (size_t)NDRUG * EMB,
                                      NPRO, EMB, 6656, 0);

    // GCN encoder
    gemm_kernel<<<dim3(4, 188), 256>>>(p_x, gc1_w, nullptr, p_xw, NTOT, H1DIM, EMB, 0);
    spmm256_kernel<<<NEDGE, 256>>>(adj_r, adj_c, adj_v, p_xw, p_h1);
    relu_kernel<<<(NTOT * H1DIM + 255) / 256, 256>>>(p_h1, NTOT * H1DIM);
    gemm_kernel<<<dim3(2, 188), 256>>>(p_h1, gc2_w, nullptr, p_t1, NTOT, H2DIM, H1DIM, 0);
    gemm_kernel<<<dim3(2, 188), 256>>>(p_h1, gc3_w, nullptr, p_t2, NTOT, H2DIM, H1DIM, 0);
    spmm128x2_kernel<<<NEDGE, 128>>>(adj_r, adj_c, adj_v, p_t1, p_t2, out_mu, out_lv);

    // decoder: adj_rec = mu @ mu^T (symmetric)
    adjsym_kernel<<<4465, 256>>>(out_mu, out);
}

// round 5
// speedup vs baseline: 1.6311x; 1.6311x over previous
#include <cuda_runtime.h>
#include <cuda_bf16.h>
#include <math.h>
#include <stdint.h>

// ---------------- problem constants ----------------
#define NDRUG   11000
#define NPRO    1000
#define NTOT    12000
#define EMB     128
#define H1DIM   256
#define H2DIM   128
#define NEDGE   192000
#define OFF_MU  144000000         // 12000*12000
#define OFF_LV  145536000         // + 12000*128
#define NT      94                // ceil(12000/128)

// decoder SMEM tile geometry
#define DPITCHB 272               // bytes per bf16 tile row (256 data + 16 pad)
#define TILEB   (128 * DPITCHB)   // 34816 bytes per tile
#define DEC_SMEM (4 * TILEB)      // 139264
#define STPITCH 132               // floats per stage row

// ---------------- scratch (__device__ globals) ----------------
__device__ float g_d1[NDRUG * EMB];
__device__ float g_d2[NDRUG * 2 * EMB];
__device__ float g_x [NTOT  * EMB];
__device__ float g_xw[NTOT  * H1DIM];
__device__ float g_h1[NTOT  * H1DIM];
__device__ float g_t1[NTOT  * H2DIM];
__device__ float g_t2[NTOT  * H2DIM];
__device__ float g_T [NPRO  * 6656];
__device__ float g_U [6656  * EMB];
__device__ float g_cb[EMB];
__device__ __nv_bfloat16 g_zhi[NTOT * EMB];
__device__ __nv_bfloat16 g_zlo[NTOT * EMB];
// CSR scratch
__device__ int   g_cnt[NTOT];
__device__ int   g_ptr[NTOT + 1];
__device__ int   g_ecol[NEDGE];
__device__ float g_eval[NEDGE];

// ---------------- helpers ----------------
__device__ __forceinline__ uint32_t smem_u32(const void* p) {
    uint32_t a;
    asm("{ .reg .u64 t; cvta.to.shared.u64 t, %1; cvt.u32.u64 %0, t; }" : "=r"(a) : "l"(p));
    return a;
}

#define LDMATRIX_X4(r0, r1, r2, r3, addr) \
    asm volatile("ldmatrix.sync.aligned.m8n8.x4.shared.b16 {%0,%1,%2,%3}, [%4];" \
                 : "=r"(r0), "=r"(r1), "=r"(r2), "=r"(r3) : "r"(addr))

#define MMA_BF16(d, a, b0, b1) \
    asm volatile("mma.sync.aligned.m16n8k16.row.col.f32.bf16.bf16.f32 " \
                 "{%0,%1,%2,%3}, {%4,%5,%6,%7}, {%8,%9}, {%0,%1,%2,%3};" \
                 : "+f"((d)[0]), "+f"((d)[1]), "+f"((d)[2]), "+f"((d)[3]) \
                 : "r"((a)[0]), "r"((a)[1]), "r"((a)[2]), "r"((a)[3]), \
                   "r"(b0), "r"(b1))

// ---------------- generic fp32 GEMM (64x64, 4x4 micro) ----------------
__global__ __launch_bounds__(256) void gemm_kernel(
    const float* __restrict__ A, const float* __restrict__ B,
    const float* __restrict__ bias, float* __restrict__ C,
    int M, int N, int K, int do_relu)
{
    __shared__ float As[16][68];
    __shared__ float Bs[16][68];
    int tid = threadIdx.x;
    int tx = tid & 15, ty = tid >> 4;
    int bm = blockIdx.y * 64, bn = blockIdx.x * 64;
    float acc[4][4] = {};

    for (int k0 = 0; k0 < K; k0 += 16) {
#pragma unroll
        for (int l = 0; l < 4; l++) {
            int e = tid + l * 256;
            int m = e >> 4, k = e & 15;
            int r = bm + m, kk = k0 + k;
            As[k][m] = (r < M && kk < K) ? A[(size_t)r * K + kk] : 0.f;
        }
#pragma unroll
        for (int l = 0; l < 4; l++) {
            int e = tid + l * 256;
            int k = e >> 6, n = e & 63;
            int kk = k0 + k, c = bn + n;
            Bs[k][n] = (kk < K && c < N) ? B[(size_t)kk * N + c] : 0.f;
        }
        __syncthreads();
#pragma unroll
        for (int k = 0; k < 16; k++) {
            float a[4], b[4];
#pragma unroll
            for (int i = 0; i < 4; i++) a[i] = As[k][ty * 4 + i];
#pragma unroll
            for (int j = 0; j < 4; j++) b[j] = Bs[k][tx * 4 + j];
#pragma unroll
            for (int i = 0; i < 4; i++)
#pragma unroll
                for (int j = 0; j < 4; j++) acc[i][j] += a[i] * b[j];
        }
        __syncthreads();
    }
#pragma unroll
    for (int i = 0; i < 4; i++) {
        int r = bm + ty * 4 + i;
        if (r >= M) continue;
#pragma unroll
        for (int j = 0; j < 4; j++) {
            int c = bn + tx * 4 + j;
            if (c >= N) continue;
            float v = acc[i][j];
            if (bias) v += bias[c];
            if (do_relu) v = fmaxf(v, 0.f);
            C[(size_t)r * N + c] = v;
        }
    }
}

// split-K GEMM: atomicAdd into C (C pre-initialized with bias)
__global__ __launch_bounds__(256) void gemm_splitk_kernel(
    const float* __restrict__ A, const float* __restrict__ B,
    float* __restrict__ C, int M, int N, int K, int kChunk)
{
    __shared__ float As[16][68];
    __shared__ float Bs[16][68];
    int tid = threadIdx.x;
    int tx = tid & 15, ty = tid >> 4;
    int bm = blockIdx.y * 64, bn = blockIdx.x * 64;
    int kBeg = blockIdx.z * kChunk;
    int kEnd = min(K, kBeg + kChunk);
    float acc[4][4] = {};

    for (int k0 = kBeg; k0 < kEnd; k0 += 16) {
#pragma unroll
        for (int l = 0; l < 4; l++) {
            int e = tid + l * 256;
            int m = e >> 4, k = e & 15;
            int r = bm + m, kk = k0 + k;
            As[k][m] = (r < M && kk < kEnd) ? A[(size_t)r * K + kk] : 0.f;
        }
#pragma unroll
        for (int l = 0; l < 4; l++) {
            int e = tid + l * 256;
            int k = e >> 6, n = e & 63;
            int kk = k0 + k, c = bn + n;
            Bs[k][n] = (kk < kEnd && c < N) ? B[(size_t)kk * N + c] : 0.f;
        }
        __syncthreads();
#pragma unroll
        for (int k = 0; k < 16; k++) {
            float a[4], b[4];
#pragma unroll
            for (int i = 0; i < 4; i++) a[i] = As[k][ty * 4 + i];
#pragma unroll
            for (int j = 0; j < 4; j++) b[j] = Bs[k][tx * 4 + j];
#pragma unroll
            for (int i = 0; i < 4; i++)
#pragma unroll
                for (int j = 0; j < 4; j++) acc[i][j] += a[i] * b[j];
        }
        __syncthreads();
    }
#pragma unroll
    for (int i = 0; i < 4; i++) {
        int r = bm + ty * 4 + i;
        if (r >= M) continue;
#pragma unroll
        for (int j = 0; j < 4; j++) {
            int c = bn + tx * 4 + j;
            if (c >= N) continue;
            atomicAdd(&C[(size_t)r * N + c], acc[i][j]);
        }
    }
}

// ---------------- protein branch ----------------
__global__ __launch_bounds__(256) void tbuild_kernel(
    const int* __restrict__ pro_x, const float* __restrict__ conv_w)
{
    __shared__ float acc[6656];
    int p = blockIdx.x, tid = threadIdx.x;
    float* a = acc + tid * 26;
#pragma unroll
    for (int v = 0; v < 26; v++) a[v] = 0.f;
    const float* cw = conv_w + (tid >> 3) * 8000 + (tid & 7);
    const int* px = pro_x + p * 1000;
#pragma unroll 4
    for (int i = 0; i < 1000; i++) {
        int v = px[i];
        a[v] += cw[i * 8];
    }
    float* out = g_T + (size_t)p * 6656 + tid * 26;
#pragma unroll
    for (int v = 0; v < 26; v++) out[v] = a[v];
}

__global__ __launch_bounds__(128) void ubuild_kernel(
    const float* __restrict__ emb_xt, const float* __restrict__ fc_w)
{
    __shared__ float emb_s[26 * 128];
    int ok = blockIdx.x;
    int o = ok >> 3, k = ok & 7;
    int e = threadIdx.x;
#pragma unroll
    for (int v = 0; v < 26; v++) emb_s[v * 128 + e] = emb_xt[v * 128 + e];
    __syncthreads();
    float acc[26];
#pragma unroll
    for (int v = 0; v < 26; v++) acc[v] = 0.f;
    for (int t = 0; t < 121; t++) {
        float f = fc_w[(size_t)(o * 121 + t) * 128 + e];
#pragma unroll
        for (int v = 0; v < 26; v++) acc[v] += f * emb_s[v * 128 + t + k];
    }
#pragma unroll
    for (int v = 0; v < 26; v++)
        g_U[(size_t)(ok * 26 + v) * 128 + e] = acc[v];
}

__global__ void cbias_kernel(const float* __restrict__ fc_w,
                             const float* __restrict__ fc_b,
                             const float* __restrict__ conv_b)
{
    int e = threadIdx.x;
    float s = fc_b[e];
    for (int o = 0; o < 32; o++) {
        float cv = conv_b[o];
#pragma unroll 4
        for (int t = 0; t < 121; t++)
            s += cv * fc_w[(size_t)(o * 121 + t) * 128 + e];
    }
    g_cb[e] = s;
}

__global__ void fill_pbias_kernel() {
    int i = blockIdx.x * blockDim.x + threadIdx.x;
    if (i < NPRO * EMB) g_x[(size_t)NDRUG * EMB + i] = g_cb[i & 127];
}

// ---------------- CSR build ----------------
__global__ void zero_cnt_kernel() {
    int i = blockIdx.x * blockDim.x + threadIdx.x;
    if (i < NTOT) g_cnt[i] = 0;
}
__global__ void hist_kernel(const int* __restrict__ rows) {
    int e = blockIdx.x * blockDim.x + threadIdx.x;
    if (e < NEDGE) atomicAdd(&g_cnt[rows[e]], 1);
}
__global__ __launch_bounds__(1024) void scan_kernel() {
    __shared__ int ssum[1024];
    int t = threadIdx.x;
    int base = t * 12;
    int loc[12];
    int run = 0;
#pragma unroll
    for (int k = 0; k < 12; k++) {
        int i = base + k;
        int v = (i < NTOT) ? g_cnt[i] : 0;
        run += v;
        loc[k] = run;
    }
    ssum[t] = run;
    __syncthreads();
    for (int d = 1; d < 1024; d <<= 1) {
        int v = (t >= d) ? ssum[t - d] : 0;
        __syncthreads();
        ssum[t] += v;
        __syncthreads();
    }
    int pref = (t > 0) ? ssum[t - 1] : 0;
    if (t == 0) g_ptr[0] = 0;
#pragma unroll
    for (int k = 0; k < 12; k++) {
        int i = base + k;
        if (i < NTOT) {
            int incl = pref + loc[k];
            int excl = pref + (k > 0 ? loc[k - 1] : 0);
            g_ptr[i + 1] = incl;
            g_cnt[i] = excl;   // cursor for scatter
        }
    }
}
__global__ void scatter_kernel(const int* __restrict__ rows, const int* __restrict__ cols,
                               const float* __restrict__ vals) {
    int e = blockIdx.x * blockDim.x + threadIdx.x;
    if (e < NEDGE) {
        int r = rows[e];
        int pos = atomicAdd(&g_cnt[r], 1);
        g_ecol[pos] = cols[e];
        g_eval[pos] = vals[e];
    }
}

// ---------------- CSR SpMM ----------------
__global__ __launch_bounds__(256) void spmm_h1_kernel() {
    int r = blockIdx.x, f = threadIdx.x;
    int s = g_ptr[r], e = g_ptr[r + 1];
    float acc = 0.f;
    for (int i = s; i < e; i++) {
        int c = g_ecol[i];
        float v = g_eval[i];
        acc += v * g_xw[(size_t)c * 256 + f];
    }
    g_h1[(size_t)r * 256 + f] = fmaxf(acc, 0.f);
}
__global__ __launch_bounds__(128) void spmm_mulv_kernel(float* __restrict__ out_mu,
                                                        float* __restrict__ out_lv) {
    int r = blockIdx.x, f = threadIdx.x;
    int s = g_ptr[r], e = g_ptr[r + 1];
    float a1 = 0.f, a2 = 0.f;
    for (int i = s; i < e; i++) {
        int c = g_ecol[i];
        float v = g_eval[i];
        a1 += v * g_t1[(size_t)c * 128 + f];
        a2 += v * g_t2[(size_t)c * 128 + f];
    }
    size_t idx = (size_t)r * 128 + f;
    out_mu[idx] = a1;
    out_lv[idx] = a2;
    __nv_bfloat16 hi = __float2bfloat16(a1);
    float lo = a1 - __bfloat162float(hi);
    g_zhi[idx] = hi;
    g_zlo[idx] = __float2bfloat16(lo);
}

// ---------------- bf16-split decoder via mma.sync (HMMA) ----------------
// C = Z Z^T, Z = zhi + zlo; acc = hi*hi^T + hi*lo^T + lo*hi^T in fp32.
// 128x128 tile per CTA, 8 warps, warp tile 32x64 (2 m-tiles x 8 n-tiles of m16n8k16).
// Symmetric: 4465 tiles (bi<=bj); mirror via transposed SMEM stage.
__global__ __launch_bounds__(256) void decoder_kernel(float* __restrict__ C)
{
    extern __shared__ char dsm[];
    const int L = blockIdx.x;
    int bi = (int)(NT + 0.5 - sqrt((NT + 0.5) * (NT + 0.5) - 2.0 * (double)L));
    if (bi < 0) bi = 0;
    while ((bi + 1) * NT - ((bi + 1) * bi) / 2 <= L) bi++;
    while (bi * NT - (bi * (bi - 1)) / 2 > L) bi--;
    int bj = bi + (L - (bi * NT - (bi * (bi - 1)) / 2));
    int r0 = bi * 128, c0 = bj * 128;

    int tid = threadIdx.x, wid = tid >> 5, lid = tid & 31;

    // ---- fill 4 SMEM tiles: {A,B} x {hi,lo}, 128 rows x 256B, pitch 272B
    {
        int row = tid >> 1, half = tid & 1;
#pragma unroll
        for (int t = 0; t < 4; t++) {
            const __nv_bfloat16* Z = (t & 1) ? g_zlo : g_zhi;
            int rb = ((t & 2) ? c0 : r0) + row;
            uint4* dst = (uint4*)(dsm + t * TILEB + row * DPITCHB + half * 128);
            if (rb < NTOT) {
                const uint4* src = (const uint4*)(Z + (size_t)rb * 128 + half * 64);
#pragma unroll
                for (int i = 0; i < 8; i++) dst[i] = src[i];
            } else {
#pragma unroll
                for (int i = 0; i < 8; i++) dst[i] = make_uint4(0, 0, 0, 0);
            }
        }
    }
    __syncthreads();

    uint32_t sbase = smem_u32(dsm);
    const uint32_t aHi = sbase, aLo = sbase + TILEB;
    const uint32_t bHi = sbase + 2 * TILEB, bLo = sbase + 3 * TILEB;
    const int warp_m = wid & 3;         // 4 warps over m (32 each)
    const int warp_n = wid >> 2;        // 2 warps over n (64 each)

    float acc[2][8][4] = {};

    // per-lane ldmatrix offsets
    const uint32_t aOff = (uint32_t)((warp_m * 32 + (lid & 15)) * DPITCHB + (lid >> 4) * 16);
    const uint32_t bOff = (uint32_t)((warp_n * 64 + ((lid >> 4) << 3) + (lid & 7)) * DPITCHB
                                     + ((lid >> 3) & 1) * 16);

#pragma unroll 1
    for (int ks = 0; ks < 8; ks++) {
        uint32_t kByte = ks * 32;
        uint32_t ah[2][4], al[2][4];
#pragma unroll
        for (int mt = 0; mt < 2; mt++) {
            uint32_t ao = aOff + mt * (16 * DPITCHB) + kByte;
            LDMATRIX_X4(ah[mt][0], ah[mt][1], ah[mt][2], ah[mt][3], aHi + ao);
            LDMATRIX_X4(al[mt][0], al[mt][1], al[mt][2], al[mt][3], aLo + ao);
        }
#pragma unroll
        for (int nb = 0; nb < 4; nb++) {
            uint32_t bo = bOff + nb * (16 * DPITCHB) + kByte;
            uint32_t bh[4], bl[4];
            LDMATRIX_X4(bh[0], bh[1], bh[2], bh[3], bHi + bo);
            LDMATRIX_X4(bl[0], bl[1], bl[2], bl[3], bLo + bo);
#pragma unroll
            for (int mt = 0; mt < 2; mt++) {
#pragma unroll
                for (int sub = 0; sub < 2; sub++) {
                    float* d = acc[mt][nb * 2 + sub];
                    MMA_BF16(d, ah[mt], bh[sub * 2], bh[sub * 2 + 1]);
                    MMA_BF16(d, ah[mt], bl[sub * 2], bl[sub * 2 + 1]);
                    MMA_BF16(d, al[mt], bh[sub * 2], bh[sub * 2 + 1]);
                }
            }
        }
    }

    // ---- epilogue
    int g = lid >> 2, tg = lid & 3;
    bool fullC = (bj < NT - 1);          // columns all in-bounds
    bool fullR = (bi < NT - 1);          // rows all in-bounds (bi==93 => bj==93)

#pragma unroll
    for (int mt = 0; mt < 2; mt++) {
#pragma unroll
        for (int nt = 0; nt < 8; nt++) {
            int m0 = warp_m * 32 + mt * 16 + g;
            int n  = c0 + warp_n * 64 + nt * 8 + tg * 2;
            int row0 = r0 + m0, row1 = row0 + 8;
            if (fullC || n + 1 < NTOT) {
                if (fullR || row0 < NTOT)
                    *(float2*)&C[(size_t)row0 * NTOT + n] = make_float2(acc[mt][nt][0], acc[mt][nt][1]);
                if (fullR || row1 < NTOT)
                    *(float2*)&C[(size_t)row1 * NTOT + n] = make_float2(acc[mt][nt][2], acc[mt][nt][3]);
            }
        }
    }

    if (bi != bj) {
        // stage transposed: st[n][m]
        float* st = (float*)dsm;
        __syncthreads();   // all SMEM tile reads done
#pragma unroll
        for (int mt = 0; mt < 2; mt++) {
#pragma unroll
            for (int nt = 0; nt < 8; nt++) {
                int m0 = warp_m * 32 + mt * 16 + g;
                int n0 = warp_n * 64 + nt * 8 + tg * 2;
                st[(n0    ) * STPITCH + m0    ] = acc[mt][nt][0];
                st[(n0 + 1) * STPITCH + m0    ] = acc[mt][nt][1];
                st[(n0    ) * STPITCH + m0 + 8] = acc[mt][nt][2];
                st[(n0 + 1) * STPITCH + m0 + 8] = acc[mt][nt][3];
            }
        }
        __syncthreads();
        // mirror: row rr = c0+j gets st[j][0..127]; coalesced float4 stores
#pragma unroll 1
        for (int it = 0; it < 16; it++) {
            int j = wid * 16 + it;
            int rr = c0 + j;
            if (rr < NTOT) {
                float4 v = *(float4*)&st[j * STPITCH + lid * 4];
                *(float4*)&C[(size_t)rr * NTOT + r0 + lid * 4] = v;
            }
        }
    }
}

// ---------------- launch ----------------
extern "C" void kernel_launch(void* const* d_in, const int* in_sizes, int n_in,
                              void* d_out, int out_size)
{
    const float* drug_x  = (const float*)d_in[0];
    const int*   pro_x   = (const int*)  d_in[1];
    const int*   adj_r   = (const int*)  d_in[2];
    const int*   adj_c   = (const int*)  d_in[3];
    const float* adj_v   = (const float*)d_in[4];
    const float* w1      = (const float*)d_in[5];
    const float* b1      = (const float*)d_in[6];
    const float* w2      = (const float*)d_in[7];
    const float* b2      = (const float*)d_in[8];
    const float* w3      = (const float*)d_in[9];
    const float* b3      = (const float*)d_in[10];
    const float* emb_xt  = (const float*)d_in[11];
    const float* conv_w  = (const float*)d_in[12];
    const float* conv_b  = (const float*)d_in[13];
    const float* fc_w    = (const float*)d_in[14];
    const float* fc_b    = (const float*)d_in[15];
    const float* gc1_w   = (const float*)d_in[16];
    const float* gc2_w   = (const float*)d_in[17];
    const float* gc3_w   = (const float*)d_in[18];

    float* out = (float*)d_out;
    float* out_mu = out + OFF_MU;
    float* out_lv = out + OFF_LV;

    float *p_d1, *p_d2, *p_x, *p_xw, *p_h1, *p_t1, *p_t2, *p_T, *p_U;
    cudaGetSymbolAddress((void**)&p_d1, g_d1);
    cudaGetSymbolAddress((void**)&p_d2, g_d2);
    cudaGetSymbolAddress((void**)&p_x,  g_x);
    cudaGetSymbolAddress((void**)&p_xw, g_xw);
    cudaGetSymbolAddress((void**)&p_h1, g_h1);
    cudaGetSymbolAddress((void**)&p_t1, g_t1);
    cudaGetSymbolAddress((void**)&p_t2, g_t2);
    cudaGetSymbolAddress((void**)&p_T,  g_T);
    cudaGetSymbolAddress((void**)&p_U,  g_U);

    cudaFuncSetAttribute(decoder_kernel, cudaFuncAttributeMaxDynamicSharedMemorySize, DEC_SMEM);

    // CSR build
    zero_cnt_kernel<<<(NTOT + 255) / 256, 256>>>();
    hist_kernel<<<NEDGE / 256, 256>>>(adj_r);
    scan_kernel<<<1, 1024>>>();
    scatter_kernel<<<NEDGE / 256, 256>>>(adj_r, adj_c, adj_v);

    // drug MLP
    gemm_kernel<<<dim3(2, 172), 256>>>(drug_x, w1, b1, p_d1, NDRUG, EMB,   167, 1);
    gemm_kernel<<<dim3(4, 172), 256>>>(p_d1,   w2, b2, p_d2, NDRUG, 2*EMB, EMB, 1);
    gemm_kernel<<<dim3(2, 172), 256>>>(p_d2,   w3, b3, p_x,  NDRUG, EMB, 2*EMB, 1);

    // protein branch (factorized conv+fc), split-K T@U
    cbias_kernel<<<1, 128>>>(fc_w, fc_b, conv_b);
    fill_pbias_kernel<<<(NPRO * EMB + 255) / 256, 256>>>();
    tbuild_kernel<<<NPRO, 256>>>(pro_x, conv_w);
    ubuild_kernel<<<256, 128>>>(emb_xt, fc_w);
    gemm_splitk_kernel<<<dim3(2, 16, 8), 256>>>(p_T, p_U, p_x + (size_t)NDRUG * EMB,
                                                NPRO, EMB, 6656, 832);

    // GCN encoder
    gemm_kernel<<<dim3(4, 188), 256>>>(p_x, gc1_w, nullptr, p_xw, NTOT, H1DIM, EMB, 0);
    spmm_h1_kernel<<<NTOT, 256>>>();
    gemm_kernel<<<dim3(2, 188), 256>>>(p_h1, gc2_w, nullptr, p_t1, NTOT, H2DIM, H1DIM, 0);
    gemm_kernel<<<dim3(2, 188), 256>>>(p_h1, gc3_w, nullptr, p_t2, NTOT, H2DIM, H1DIM, 0);
    spmm_mulv_kernel<<<NTOT, 128>>>(out_mu, out_lv);

    // decoder: adj_rec = mu @ mu^T via bf16-split mma.sync (symmetric)
    decoder_kernel<<<(NT * (NT + 1)) / 2, 256, DEC_SMEM>>>(out);
}

// round 8
// speedup vs baseline: 1.8202x; 1.1159x over previous
#include <cuda_runtime.h>
#include <cuda_bf16.h>
#include <math.h>
#include <stdint.h>

// ---------------- problem constants ----------------
#define NDRUG   11000
#define NPRO    1000
#define NTOT    12000
#define EMB     128
#define H1DIM   256
#define H2DIM   128
#define NEDGE   192000
#define OFF_MU  144000000         // 12000*12000
#define OFF_LV  145536000         // + 12000*128
#define NT      94                // ceil(12000/128)

// decoder SMEM tile geometry
#define DPITCHB 272               // bytes per bf16 tile row (256 data + 16 pad)
#define TILEB   (128 * DPITCHB)   // 34816 bytes per tile
#define DEC_SMEM (4 * TILEB)      // 139264
#define STPITCH 132               // floats per stage row

// mma-GEMM SMEM geometry (BK=64)
#define APITCH  72                // bf16 per A row (64 data + 8 pad)
#define BPITCH  136               // bf16 per B row (128 data + 8 pad)
#define A_BUF_B (128 * APITCH * 2)   // 18432 bytes per (hi|lo) buffer
#define B_BUF_B (64 * BPITCH * 2)    // 17408
#define G_SMEM  (2 * A_BUF_B + 2 * B_BUF_B)   // 71680

// ---------------- scratch (__device__ globals) ----------------
__device__ float g_d1[NDRUG * EMB];
__device__ float g_d2[NDRUG * 2 * EMB];
__device__ float g_x [NTOT  * EMB];
__device__ float g_xw[NTOT  * H1DIM];
__device__ float g_h1[NTOT  * H1DIM];
__device__ float g_t12[NTOT * 256];        // [t1 | t2] fused
__device__ float g_w23[256 * 256];         // [gc2_w | gc3_w] packed
__device__ float g_T [NPRO  * 6656];
__device__ float g_U [6656  * EMB];
__device__ float g_cb[EMB];
__device__ __nv_bfloat16 g_zhi[NTOT * EMB];
__device__ __nv_bfloat16 g_zlo[NTOT * EMB];
// CSR scratch
__device__ int   g_cnt[NTOT];
__device__ int   g_ptr[NTOT + 1];
__device__ int   g_ecol[NEDGE];
__device__ float g_eval[NEDGE];

// ---------------- helpers ----------------
__device__ __forceinline__ uint32_t smem_u32(const void* p) {
    uint32_t a;
    asm("{ .reg .u64 t; cvta.to.shared.u64 t, %1; cvt.u32.u64 %0, t; }" : "=r"(a) : "l"(p));
    return a;
}

#define LDMATRIX_X4(r0, r1, r2, r3, addr) \
    asm volatile("ldmatrix.sync.aligned.m8n8.x4.shared.b16 {%0,%1,%2,%3}, [%4];" \
                 : "=r"(r0), "=r"(r1), "=r"(r2), "=r"(r3) : "r"(addr))

#define LDMATRIX_X4T(r0, r1, r2, r3, addr) \
    asm volatile("ldmatrix.sync.aligned.m8n8.x4.trans.shared.b16 {%0,%1,%2,%3}, [%4];" \
                 : "=r"(r0), "=r"(r1), "=r"(r2), "=r"(r3) : "r"(addr))

#define MMA_BF16(d, a, b0, b1) \
    asm volatile("mma.sync.aligned.m16n8k16.row.col.f32.bf16.bf16.f32 " \
                 "{%0,%1,%2,%3}, {%4,%5,%6,%7}, {%8,%9}, {%0,%1,%2,%3};" \
                 : "+f"((d)[0]), "+f"((d)[1]), "+f"((d)[2]), "+f"((d)[3]) \
                 : "r"((a)[0]), "r"((a)[1]), "r"((a)[2]), "r"((a)[3]), \
                   "r"(b0), "r"(b1))

// ================= bf16-split tensor-core GEMM =================
// C[M,N] = A[M,K] @ B[K,N] (+bias, relu). A,B fp32 row-major, converted
// to bf16 hi/lo in SMEM; acc = Ah*Bh + Ah*Bl + Al*Bh in fp32.
// CTA tile 128x128, BK=64, 256 threads (8 warps, warp tile 32x64).
// N must be a multiple of 128 at launch granularity (bn tiles exact).
__device__ __forceinline__ void gemm_mma_body(
    const float* __restrict__ A, const float* __restrict__ B,
    const float* __restrict__ bias, float* __restrict__ C,
    int M, int N, int K, int do_relu, int kBeg, int kEnd, int use_atomic)
{
    extern __shared__ char gsm[];
    __nv_bfloat16* sAhi = (__nv_bfloat16*)gsm;
    __nv_bfloat16* sAlo = sAhi + 128 * APITCH;
    __nv_bfloat16* sBhi = (__nv_bfloat16*)(gsm + 2 * A_BUF_B);
    __nv_bfloat16* sBlo = sBhi + 64 * BPITCH;

    const int tid = threadIdx.x, lid = tid & 31, wid = tid >> 5;
    const int warp_m = wid & 3, warp_n = wid >> 2;
    const int bm = blockIdx.y * 128, bn = blockIdx.x * 128;

    const uint32_t aHiB = smem_u32(sAhi), aLoB = smem_u32(sAlo);
    const uint32_t bHiB = smem_u32(sBhi), bLoB = smem_u32(sBlo);

    // ldmatrix lane addressing
    const uint32_t aOff = (uint32_t)((warp_m * 32 + (lid & 15)) * (APITCH * 2) + (lid >> 4) * 16);
    const int quad = lid >> 3, riq = lid & 7;
    const uint32_t bOff = (uint32_t)(((quad & 1) * 8 + riq) * (BPITCH * 2)
                                     + (warp_n * 64 + (quad >> 1) * 8) * 2);

    float acc[2][8][4] = {};

    for (int k0 = kBeg; k0 < kEnd; k0 += 64) {
        __syncthreads();
        // ---- load + convert A tile (128 x 64)
#pragma unroll
        for (int p = 0; p < 32; p++) {
            int e = p * 256 + tid;
            int r = e >> 6, k = e & 63;
            int gr = bm + r, gk = k0 + k;
            float v = (gr < M && gk < kEnd) ? A[(size_t)gr * K + gk] : 0.f;
            __nv_bfloat16 h = __float2bfloat16(v);
            sAhi[r * APITCH + k] = h;
            sAlo[r * APITCH + k] = __float2bfloat16(v - __bfloat162float(h));
        }
        // ---- load + convert B tile (64 x 128)
#pragma unroll
        for (int p = 0; p < 32; p++) {
            int e = p * 256 + tid;
            int k = e >> 7, n = e & 127;
            int gk = k0 + k;
            float v = (gk < kEnd) ? B[(size_t)gk * N + bn + n] : 0.f;
            __nv_bfloat16 h = __float2bfloat16(v);
            sBhi[k * BPITCH + n] = h;
            sBlo[k * BPITCH + n] = __float2bfloat16(v - __bfloat162float(h));
        }
        __syncthreads();

        // ---- mma phase: 4 k-steps of 16
#pragma unroll
        for (int ks = 0; ks < 4; ks++) {
            uint32_t ah[2][4], al[2][4];
#pragma unroll
            for (int mt = 0; mt < 2; mt++) {
                uint32_t ao = aOff + mt * (16 * APITCH * 2) + ks * 32;
                LDMATRIX_X4(ah[mt][0], ah[mt][1], ah[mt][2], ah[mt][3], aHiB + ao);
                LDMATRIX_X4(al[mt][0], al[mt][1], al[mt][2], al[mt][3], aLoB + ao);
            }
#pragma unroll
            for (int ng = 0; ng < 4; ng++) {
                uint32_t bo = bOff + ks * (16 * BPITCH * 2) + ng * 32;
                uint32_t bh[4], bl[4];
                LDMATRIX_X4T(bh[0], bh[1], bh[2], bh[3], bHiB + bo);
                LDMATRIX_X4T(bl[0], bl[1], bl[2], bl[3], bLoB + bo);
#pragma unroll
                for (int mt = 0; mt < 2; mt++) {
                    float* d0 = acc[mt][ng * 2];
                    float* d1 = acc[mt][ng * 2 + 1];
                    MMA_BF16(d0, ah[mt], bh[0], bh[1]);
                    MMA_BF16(d0, ah[mt], bl[0], bl[1]);
                    MMA_BF16(d0, al[mt], bh[0], bh[1]);
                    MMA_BF16(d1, ah[mt], bh[2], bh[3]);
                    MMA_BF16(d1, ah[mt], bl[2], bl[3]);
                    MMA_BF16(d1, al[mt], bh[2], bh[3]);
                }
            }
        }
    }

    // ---- epilogue
    const int g = lid >> 2, tg = lid & 3;
#pragma unroll
    for (int mt = 0; mt < 2; mt++) {
#pragma unroll
        for (int nt = 0; nt < 8; nt++) {
            int r0 = bm + warp_m * 32 + mt * 16 + g;
            int c  = bn + warp_n * 64 + nt * 8 + tg * 2;
            float bz0 = bias ? bias[c] : 0.f;
            float bz1 = bias ? bias[c + 1] : 0.f;
            float v0 = acc[mt][nt][0] + bz0, v1 = acc[mt][nt][1] + bz1;
            float v2 = acc[mt][nt][2] + bz0, v3 = acc[mt][nt][3] + bz1;
            if (do_relu) {
                v0 = fmaxf(v0, 0.f); v1 = fmaxf(v1, 0.f);
                v2 = fmaxf(v2, 0.f); v3 = fmaxf(v3, 0.f);
            }
            if (use_atomic) {
                if (r0 < M) {
                    atomicAdd(&C[(size_t)r0 * N + c], v0);
                    atomicAdd(&C[(size_t)r0 * N + c + 1], v1);
                }
                if (r0 + 8 < M) {
                    atomicAdd(&C[(size_t)(r0 + 8) * N + c], v2);
                    atomicAdd(&C[(size_t)(r0 + 8) * N + c + 1], v3);
                }
            } else {
                if (r0 < M)
                    *(float2*)&C[(size_t)r0 * N + c] = make_float2(v0, v1);
                if (r0 + 8 < M)
                    *(float2*)&C[(size_t)(r0 + 8) * N + c] = make_float2(v2, v3);
            }
        }
    }
}

__global__ __launch_bounds__(256) void gemm_mma_kernel(
    const float* __restrict__ A, const float* __restrict__ B,
    const float* __restrict__ bias, float* __restrict__ C,
    int M, int N, int K, int do_relu)
{
    gemm_mma_body(A, B, bias, C, M, N, K, do_relu, 0, K, 0);
}

__global__ __launch_bounds__(256) void gemm_mma_splitk_kernel(
    const float* __restrict__ A, const float* __restrict__ B,
    float* __restrict__ C, int M, int N, int K, int kChunk)
{
    int kBeg = blockIdx.z * kChunk;
    int kEnd = min(K, kBeg + kChunk);
    gemm_mma_body(A, B, nullptr, C, M, N, K, 0, kBeg, kEnd, 1);
}

// ---------------- protein branch ----------------
__global__ __launch_bounds__(256) void tbuild_kernel(
    const int* __restrict__ pro_x, const float* __restrict__ conv_w)
{
    __shared__ float acc[6656];
    int p = blockIdx.x, tid = threadIdx.x;
    float* a = acc + tid * 26;
#pragma unroll
    for (int v = 0; v < 26; v++) a[v] = 0.f;
    const float* cw = conv_w + (tid >> 3) * 8000 + (tid & 7);
    const int* px = pro_x + p * 1000;
#pragma unroll 4
    for (int i = 0; i < 1000; i++) {
        int v = px[i];
        a[v] += cw[i * 8];
    }
    float* out = g_T + (size_t)p * 6656 + tid * 26;
#pragma unroll
    for (int v = 0; v < 26; v++) out[v] = a[v];
}

__global__ __launch_bounds__(128) void ubuild_kernel(
    const float* __restrict__ emb_xt, const float* __restrict__ fc_w)
{
    __shared__ float emb_s[26 * 128];
    int ok = blockIdx.x;
    int o = ok >> 3, k = ok & 7;
    int e = threadIdx.x;
#pragma unroll
    for (int v = 0; v < 26; v++) emb_s[v * 128 + e] = emb_xt[v * 128 + e];
    __syncthreads();
    float acc[26];
#pragma unroll
    for (int v = 0; v < 26; v++) acc[v] = 0.f;
    for (int t = 0; t < 121; t++) {
        float f = fc_w[(size_t)(o * 121 + t) * 128 + e];
#pragma unroll
        for (int v = 0; v < 26; v++) acc[v] += f * emb_s[v * 128 + t + k];
    }
#pragma unroll
    for (int v = 0; v < 26; v++)
        g_U[(size_t)(ok * 26 + v) * 128 + e] = acc[v];
}

__global__ void cbias_kernel(const float* __restrict__ fc_w,
                             const float* __restrict__ fc_b,
                             const float* __restrict__ conv_b)
{
    int e = threadIdx.x;
    float s = fc_b[e];
    for (int o = 0; o < 32; o++) {
        float cv = conv_b[o];
#pragma unroll 4
        for (int t = 0; t < 121; t++)
            s += cv * fc_w[(size_t)(o * 121 + t) * 128 + e];
    }
    g_cb[e] = s;
}

__global__ void fill_pbias_kernel() {
    int i = blockIdx.x * blockDim.x + threadIdx.x;
    if (i < NPRO * EMB) g_x[(size_t)NDRUG * EMB + i] = g_cb[i & 127];
}

__global__ void pack_w23_kernel(const float* __restrict__ gc2_w,
                                const float* __restrict__ gc3_w)
{
    int i = blockIdx.x * blockDim.x + threadIdx.x;   // 65536
    int k = i >> 8, n = i & 255;
    g_w23[i] = (n < 128) ? gc2_w[k * 128 + n] : gc3_w[k * 128 + (n - 128)];
}

// ---------------- CSR build ----------------
__global__ void zero_cnt_kernel() {
    int i = blockIdx.x * blockDim.x + threadIdx.x;
    if (i < NTOT) g_cnt[i] = 0;
}
__global__ void hist_kernel(const int* __restrict__ rows) {
    int e = blockIdx.x * blockDim.x + threadIdx.x;
    if (e < NEDGE) atomicAdd(&g_cnt[rows[e]], 1);
}
__global__ __launch_bounds__(1024) void scan_kernel() {
    __shared__ int ssum[1024];
    int t = threadIdx.x;
    int base = t * 12;
    int loc[12];
    int run = 0;
#pragma unroll
    for (int k = 0; k < 12; k++) {
        int i = base + k;
        int v = (i < NTOT) ? g_cnt[i] : 0;
        run += v;
        loc[k] = run;
    }
    ssum[t] = run;
    __syncthreads();
    for (int d = 1; d < 1024; d <<= 1) {
        int v = (t >= d) ? ssum[t - d] : 0;
        __syncthreads();
        ssum[t] += v;
        __syncthreads();
    }
    int pref = (t > 0) ? ssum[t - 1] : 0;
    if (t == 0) g_ptr[0] = 0;
#pragma unroll
    for (int k = 0; k < 12; k++) {
        int i = base + k;
        if (i < NTOT) {
            int incl = pref + loc[k];
            int excl = pref + (k > 0 ? loc[k - 1] : 0);
            g_ptr[i + 1] = incl;
            g_cnt[i] = excl;
        }
    }
}
__global__ void scatter_kernel(const int* __restrict__ rows, const int* __restrict__ cols,
                               const float* __restrict__ vals) {
    int e = blockIdx.x * blockDim.x + threadIdx.x;
    if (e < NEDGE) {
        int r = rows[e];
        int pos = atomicAdd(&g_cnt[r], 1);
        g_ecol[pos] = cols[e];
        g_eval[pos] = vals[e];
    }
}

// ---------------- CSR SpMM ----------------
__global__ __launch_bounds__(256) void spmm_h1_kernel() {
    int r = blockIdx.x, f = threadIdx.x;
    int s = g_ptr[r], e = g_ptr[r + 1];
    float acc = 0.f;
    for (int i = s; i < e; i++) {
        int c = g_ecol[i];
        float v = g_eval[i];
        acc += v * g_xw[(size_t)c * 256 + f];
    }
    g_h1[(size_t)r * 256 + f] = fmaxf(acc, 0.f);
}
__global__ __launch_bounds__(128) void spmm_mulv_kernel(float* __restrict__ out_mu,
                                                        float* __restrict__ out_lv) {
    int r = blockIdx.x, f = threadIdx.x;
    int s = g_ptr[r], e = g_ptr[r + 1];
    float a1 = 0.f, a2 = 0.f;
    for (int i = s; i < e; i++) {
        int c = g_ecol[i];
        float v = g_eval[i];
        a1 += v * g_t12[(size_t)c * 256 + f];
        a2 += v * g_t12[(size_t)c * 256 + 128 + f];
    }
    size_t idx = (size_t)r * 128 + f;
    out_mu[idx] = a1;
    out_lv[idx] = a2;
    __nv_bfloat16 hi = __float2bfloat16(a1);
    float lo = a1 - __bfloat162float(hi);
    g_zhi[idx] = hi;
    g_zlo[idx] = __float2bfloat16(lo);
}

// ---------------- bf16-split decoder via mma.sync ----------------
__global__ __launch_bounds__(256) void decoder_kernel(float* __restrict__ C)
{
    extern __shared__ char dsm[];
    const int L = blockIdx.x;
    int bi = (int)(NT + 0.5 - sqrt((NT + 0.5) * (NT + 0.5) - 2.0 * (double)L));
    if (bi < 0) bi = 0;
    while ((bi + 1) * NT - ((bi + 1) * bi) / 2 <= L) bi++;
    while (bi * NT - (bi * (bi - 1)) / 2 > L) bi--;
    int bj = bi + (L - (bi * NT - (bi * (bi - 1)) / 2));
    int r0 = bi * 128, c0 = bj * 128;

    int tid = threadIdx.x, wid = tid >> 5, lid = tid & 31;

    {
        int row = tid >> 1, half = tid & 1;
#pragma unroll
        for (int t = 0; t < 4; t++) {
            const __nv_bfloat16* Z = (t & 1) ? g_zlo : g_zhi;
            int rb = ((t & 2) ? c0 : r0) + row;
            uint4* dst = (uint4*)(dsm + t * TILEB + row * DPITCHB + half * 128);
            if (rb < NTOT) {
                const uint4* src = (const uint4*)(Z + (size_t)rb * 128 + half * 64);
#pragma unroll
                for (int i = 0; i < 8; i++) dst[i] = src[i];
            } else {
#pragma unroll
                for (int i = 0; i < 8; i++) dst[i] = make_uint4(0, 0, 0, 0);
            }
        }
    }
    __syncthreads();

    uint32_t sbase = smem_u32(dsm);
    const uint32_t aHi = sbase, aLo = sbase + TILEB;
    const uint32_t bHi = sbase + 2 * TILEB, bLo = sbase + 3 * TILEB;
    const int warp_m = wid & 3;
    const int warp_n = wid >> 2;

    float acc[2][8][4] = {};

    const uint32_t aOff = (uint32_t)((warp_m * 32 + (lid & 15)) * DPITCHB + (lid >> 4) * 16);
    const uint32_t bOff = (uint32_t)((warp_n * 64 + ((lid >> 4) << 3) + (lid & 7)) * DPITCHB
                                     + ((lid >> 3) & 1) * 16);

#pragma unroll 1
    for (int ks = 0; ks < 8; ks++) {
        uint32_t kByte = ks * 32;
        uint32_t ah[2][4], al[2][4];
#pragma unroll
        for (int mt = 0; mt < 2; mt++) {
            uint32_t ao = aOff + mt * (16 * DPITCHB) + kByte;
            LDMATRIX_X4(ah[mt][0], ah[mt][1], ah[mt][2], ah[mt][3], aHi + ao);
            LDMATRIX_X4(al[mt][0], al[mt][1], al[mt][2], al[mt][3], aLo + ao);
        }
#pragma unroll
        for (int nb = 0; nb < 4; nb++) {
            uint32_t bo = bOff + nb * (16 * DPITCHB) + kByte;
            uint32_t bh[4], bl[4];
            LDMATRIX_X4(bh[0], bh[1], bh[2], bh[3], bHi + bo);
            LDMATRIX_X4(bl[0], bl[1], bl[2], bl[3], bLo + bo);
#pragma unroll
            for (int mt = 0; mt < 2; mt++) {
#pragma unroll
                for (int sub = 0; sub < 2; sub++) {
                    float* d = acc[mt][nb * 2 + sub];
                    MMA_BF16(d, ah[mt], bh[sub * 2], bh[sub * 2 + 1]);
                    MMA_BF16(d, ah[mt], bl[sub * 2], bl[sub * 2 + 1]);
                    MMA_BF16(d, al[mt], bh[sub * 2], bh[sub * 2 + 1]);
                }
            }
        }
    }

    int g = lid >> 2, tg = lid & 3;
    bool fullC = (bj < NT - 1);
    bool fullR = (bi < NT - 1);

#pragma unroll
    for (int mt = 0; mt < 2; mt++) {
#pragma unroll
        for (int nt = 0; nt < 8; nt++) {
            int m0 = warp_m * 32 + mt * 16 + g;
            int n  = c0 + warp_n * 64 + nt * 8 + tg * 2;
            int row0 = r0 + m0, row1 = row0 + 8;
            if (fullC || n + 1 < NTOT) {
                if (fullR || row0 < NTOT)
                    *(float2*)&C[(size_t)row0 * NTOT + n] = make_float2(acc[mt][nt][0], acc[mt][nt][1]);
                if (fullR || row1 < NTOT)
                    *(float2*)&C[(size_t)row1 * NTOT + n] = make_float2(acc[mt][nt][2], acc[mt][nt][3]);
            }
        }
    }

    if (bi != bj) {
        float* st = (float*)dsm;
        __syncthreads();
#pragma unroll
        for (int mt = 0; mt < 2; mt++) {
#pragma unroll
            for (int nt = 0; nt < 8; nt++) {
                int m0 = warp_m * 32 + mt * 16 + g;
                int n0 = warp_n * 64 + nt * 8 + tg * 2;
                st[(n0    ) * STPITCH + m0    ] = acc[mt][nt][0];
                st[(n0 + 1) * STPITCH + m0    ] = acc[mt][nt][1];
                st[(n0    ) * STPITCH + m0 + 8] = acc[mt][nt][2];
                st[(n0 + 1) * STPITCH + m0 + 8] = acc[mt][nt][3];
            }
        }
        __syncthreads();
#pragma unroll 1
        for (int it = 0; it < 16; it++) {
            int j = wid * 16 + it;
            int rr = c0 + j;
            if (rr < NTOT) {
                float4 v = *(float4*)&st[j * STPITCH + lid * 4];
                *(float4*)&C[(size_t)rr * NTOT + r0 + lid * 4] = v;
            }
        }
    }
}

// ---------------- launch ----------------
extern "C" void kernel_launch(void* const* d_in, const int* in_sizes, int n_in,
                              void* d_out, int out_size)
{
    const float* drug_x  = (const float*)d_in[0];
    const int*   pro_x   = (const int*)  d_in[1];
    const int*   adj_r   = (const int*)  d_in[2];
    const int*   adj_c   = (const int*)  d_in[3];
    const float* adj_v   = (const float*)d_in[4];
    const float* w1      = (const float*)d_in[5];
    const float* b1      = (const float*)d_in[6];
    const float* w2      = (const float*)d_in[7];
    const float* b2      = (const float*)d_in[8];
    const float* w3      = (const float*)d_in[9];
    const float* b3      = (const float*)d_in[10];
    const float* emb_xt  = (const float*)d_in[11];
    const float* conv_w  = (const float*)d_in[12];
    const float* conv_b  = (const float*)d_in[13];
    const float* fc_w    = (const float*)d_in[14];
    const float* fc_b    = (const float*)d_in[15];
    const float* gc1_w   = (const float*)d_in[16];
    const float* gc2_w   = (const float*)d_in[17];
    const float* gc3_w   = (const float*)d_in[18];

    float* out = (float*)d_out;
    float* out_mu = out + OFF_MU;
    float* out_lv = out + OFF_LV;

    float *p_d1, *p_d2, *p_x, *p_xw, *p_h1, *p_t12, *p_w23, *p_T, *p_U;
    cudaGetSymbolAddress((void**)&p_d1, g_d1);
    cudaGetSymbolAddress((void**)&p_d2, g_d2);
    cudaGetSymbolAddress((void**)&p_x,  g_x);
    cudaGetSymbolAddress((void**)&p_xw, g_xw);
    cudaGetSymbolAddress((void**)&p_h1, g_h1);
    cudaGetSymbolAddress((void**)&p_t12, g_t12);
    cudaGetSymbolAddress((void**)&p_w23, g_w23);
    cudaGetSymbolAddress((void**)&p_T,  g_T);
    cudaGetSymbolAddress((void**)&p_U,  g_U);

    cudaFuncSetAttribute(decoder_kernel, cudaFuncAttributeMaxDynamicSharedMemorySize, DEC_SMEM);
    cudaFuncSetAttribute(gemm_mma_kernel, cudaFuncAttributeMaxDynamicSharedMemorySize, G_SMEM);
    cudaFuncSetAttribute(gemm_mma_splitk_kernel, cudaFuncAttributeMaxDynamicSharedMemorySize, G_SMEM);

    // CSR build
    zero_cnt_kernel<<<(NTOT + 255) / 256, 256>>>();
    hist_kernel<<<NEDGE / 256, 256>>>(adj_r);
    scan_kernel<<<1, 1024>>>();
    scatter_kernel<<<NEDGE / 256, 256>>>(adj_r, adj_c, adj_v);

    // drug MLP (bf16-split mma)
    gemm_mma_kernel<<<dim3(1, 86), 256, G_SMEM>>>(drug_x, w1, b1, p_d1, NDRUG, 128, 167, 1);
    gemm_mma_kernel<<<dim3(2, 86), 256, G_SMEM>>>(p_d1,   w2, b2, p_d2, NDRUG, 256, 128, 1);
    gemm_mma_kernel<<<dim3(1, 86), 256, G_SMEM>>>(p_d2,   w3, b3, p_x,  NDRUG, 128, 256, 1);

    // protein branch (factorized conv+fc), split-K T@U
    cbias_kernel<<<1, 128>>>(fc_w, fc_b, conv_b);
    fill_pbias_kernel<<<(NPRO * EMB + 255) / 256, 256>>>();
    tbuild_kernel<<<NPRO, 256>>>(pro_x, conv_w);
    ubuild_kernel<<<256, 128>>>(emb_xt, fc_w);
    gemm_mma_splitk_kernel<<<dim3(1, 8, 13), 256, G_SMEM>>>(p_T, p_U, p_x + (size_t)NDRUG * EMB,
                                                            NPRO, 128, 6656, 512);

    // GCN encoder
    pack_w23_kernel<<<256, 256>>>(gc2_w, gc3_w);
    gemm_mma_kernel<<<dim3(2, 94), 256, G_SMEM>>>(p_x, gc1_w, nullptr, p_xw, NTOT, 256, 128, 0);
    spmm_h1_kernel<<<NTOT, 256>>>();
    gemm_mma_kernel<<<dim3(2, 94), 256, G_SMEM>>>(p_h1, p_w23, nullptr, p_t12, NTOT, 256, 256, 0);
    spmm_mulv_kernel<<<NTOT, 128>>>(out_mu, out_lv);

    // decoder
    decoder_kernel<<<(NT * (NT + 1)) / 2, 256, DEC_SMEM>>>(out);
}